// round 3
// baseline (speedup 1.0000x reference)
#include <cuda_runtime.h>
#include <math.h>

#define N_NODES  50000
#define N_EDGES  800000
#define N_GRAPHS 64
#define SCAN_B   1024
#define NB_SCAN  ((N_NODES + SCAN_B - 1) / SCAN_B)   // 49

// ---------------- scratch (device globals; no allocation allowed) ----------
__device__ __align__(16) float g_h0[N_NODES * 256];
__device__ __align__(16) float g_agg1[N_NODES * 256];
__device__ __align__(16) float g_h1[N_NODES * 256];
__device__ __align__(16) float g_p1[N_NODES * 128];
__device__ __align__(16) float g_q1[N_NODES * 128];
__device__ float g_dinv[N_NODES];
__device__ int   g_cnt[N_NODES];
__device__ int   g_rowstart[N_NODES];
__device__ int   g_cursor[N_NODES];
__device__ int   g_inlist[N_EDGES];
__device__ float g_gsum[N_GRAPHS * 128];
__device__ int   g_gcnt[N_GRAPHS];
__device__ int   g_bsums[64];

// dtype flags + device-side scratch pointer table (filled in k_init; avoids
// any host-side symbol-address semantics entirely)
__device__ int    g_ei64;
__device__ int    g_b64;
__device__ float* g_ptrs[5];   // 0:h0 1:agg1 2:h1 3:p1 4:q1

// int64-or-int32 index accessor
__device__ __forceinline__ int ld_idx(const void* p, long long i, int is64) {
    return is64 ? (int)((const long long*)p)[i] : ((const int*)p)[i];
}

// ---------------- init: dtype detection + pointer table ---------------------
// Reads only 32-bit words that are in-bounds under the SMALLEST (int32)
// interpretation of each buffer, so this is safe for either dtype.
__global__ void k_init(const int* ei_w, const int* b_w) {
    if (threadIdx.x == 0 && blockIdx.x == 0) {
        // edge_index: odd words 1..127. int64 -> high halves, all 0.
        // int32 -> random node ids, ~never all 0.
        int a = 1;
        for (int k = 0; k < 64; k++) if (ei_w[2 * k + 1] != 0) { a = 0; break; }
        g_ei64 = a;
        // batch (sorted, tail = graph ~63): odd words 49001..49127.
        // int64 -> high halves of entries ~24500..24563, all 0.
        // int32 -> graph ids ~62-63, nonzero.
        a = 1;
        for (int k = 0; k < 64; k++) if (b_w[49001 + 2 * k] != 0) { a = 0; break; }
        g_b64 = a;

        g_ptrs[0] = g_h0;
        g_ptrs[1] = g_agg1;
        g_ptrs[2] = g_h1;
        g_ptrs[3] = g_p1;
        g_ptrs[4] = g_q1;
    }
}

// ---------------- zero ------------------------------------------------------
__global__ void k_zero() {
    int i = blockIdx.x * blockDim.x + threadIdx.x;
    int stride = gridDim.x * blockDim.x;
    for (int j = i; j < N_NODES; j += stride) g_cnt[j] = 0;
    for (int j = i; j < N_GRAPHS * 128; j += stride) g_gsum[j] = 0.0f;
    for (int j = i; j < N_GRAPHS; j += stride) g_gcnt[j] = 0;
}

// ---------------- CSR build -------------------------------------------------
__global__ void k_count(const void* __restrict__ ei) {
    int is64 = g_ei64;
    int i = blockIdx.x * blockDim.x + threadIdx.x;
    int stride = gridDim.x * blockDim.x;
    for (int e = i; e < N_EDGES; e += stride) {
        int d = ld_idx(ei, (long long)N_EDGES + e, is64);
        atomicAdd(&g_cnt[d], 1);
    }
}

__global__ void k_scan1() {
    __shared__ int s[SCAN_B];
    int i = blockIdx.x * SCAN_B + threadIdx.x;
    int v = (i < N_NODES) ? g_cnt[i] : 0;
    s[threadIdx.x] = v;
    __syncthreads();
    for (int off = 1; off < SCAN_B; off <<= 1) {
        int t = (threadIdx.x >= off) ? s[threadIdx.x - off] : 0;
        __syncthreads();
        s[threadIdx.x] += t;
        __syncthreads();
    }
    if (i < N_NODES) g_rowstart[i] = s[threadIdx.x];
    if (threadIdx.x == SCAN_B - 1) g_bsums[blockIdx.x] = s[SCAN_B - 1];
}

__global__ void k_scan2() {
    int run = 0;
    for (int b = 0; b < NB_SCAN; b++) {
        int t = g_bsums[b];
        g_bsums[b] = run;
        run += t;
    }
}

__global__ void k_scan3() {
    int i = blockIdx.x * SCAN_B + threadIdx.x;
    if (i >= N_NODES) return;
    int incl = g_rowstart[i];
    int excl = incl - g_cnt[i] + g_bsums[i >> 10];
    g_rowstart[i] = excl;
    g_cursor[i] = excl;
}

__global__ void k_scatter(const void* __restrict__ ei) {
    int is64 = g_ei64;
    int i = blockIdx.x * blockDim.x + threadIdx.x;
    int stride = gridDim.x * blockDim.x;
    for (int e = i; e < N_EDGES; e += stride) {
        int s = ld_idx(ei, e, is64);
        int d = ld_idx(ei, (long long)N_EDGES + e, is64);
        int pos = atomicAdd(&g_cursor[d], 1);
        g_inlist[pos] = s;
    }
}

// ---------------- layer 0 (rank-1): warp per node ---------------------------
__global__ void k_layer0(const float* __restrict__ x,
                         const float* __restrict__ Wl0,
                         const float* __restrict__ b0,
                         const float* __restrict__ Wr0) {
    int wid = (blockIdx.x * blockDim.x + threadIdx.x) >> 5;
    int lane = threadIdx.x & 31;
    if (wid >= N_NODES) return;
    int deg = g_cnt[wid];
    int start = g_rowstart[wid];
    float s = 0.0f;
    for (int i = lane; i < deg; i += 32) s += x[g_inlist[start + i]];
    #pragma unroll
    for (int o = 16; o; o >>= 1) s += __shfl_xor_sync(0xFFFFFFFFu, s, o);
    float dinv = 1.0f / fmaxf((float)deg, 1.0f);
    if (lane == 0) g_dinv[wid] = dinv;
    float agg = s * dinv;
    float xv = x[wid];
    #pragma unroll
    for (int i = 0; i < 8; i++) {
        int f = i * 32 + lane;
        float v = fmaf(agg, Wl0[f], fmaf(xv, Wr0[f], b0[f]));
        g_h0[wid * 256 + f] = fmaxf(v, 0.0f);
    }
}

// ---------------- gather (mean-aggregate h0 -> agg1*dinv): block per node ---
__global__ void k_gather1() {
    int n = blockIdx.x;
    int f = threadIdx.x;
    int deg = g_cnt[n];
    int start = g_rowstart[n];
    __shared__ int es[256];
    float acc = 0.0f;
    for (int base = 0; base < deg; base += 256) {
        int m = min(256, deg - base);
        __syncthreads();
        if (f < m) es[f] = g_inlist[start + base + f];
        __syncthreads();
        for (int e = 0; e < m; e++) acc += g_h0[es[e] * 256 + f];
    }
    g_agg1[n * 256 + f] = acc * g_dinv[n];
}

// ---------------- fused SGEMM: C = act([A0|A1] @ [B0;B1] + bias) ------------
// A0/A1/C selected from the device-side pointer table (selA1 < 0 -> unused).
// BM=BN=128, BK=8, 256 threads, 8x8 per thread.
__global__ void __launch_bounds__(256, 2)
k_sgemm(int selA0, int K0, int selA1, int K1,
        const float* __restrict__ B0, const float* __restrict__ B1,
        const float* __restrict__ bias, int selC,
        int nrows, int ncols, int relu) {
    const float* A0 = g_ptrs[selA0];
    const float* A1 = (selA1 >= 0) ? g_ptrs[selA1] : (const float*)0;
    float* C = g_ptrs[selC];

    __shared__ float As[8][128];
    __shared__ float Bs[8][128];

    int tid = threadIdx.x;
    int tx = tid & 15;
    int ty = tid >> 4;
    int rowBase = blockIdx.y * 128;
    int colBase = blockIdx.x * 128;
    int K = K0 + K1;

    float acc[8][8];
    #pragma unroll
    for (int i = 0; i < 8; i++)
        #pragma unroll
        for (int j = 0; j < 8; j++) acc[i][j] = 0.0f;

    int a_m = tid >> 1;
    int a_k = (tid & 1) * 4;
    int b_k = tid >> 5;
    int b_n = (tid & 31) * 4;

    for (int k0 = 0; k0 < K; k0 += 8) {
        // A tile: 128 rows x 8 k
        {
            int row = rowBase + a_m;
            float4 v = make_float4(0.f, 0.f, 0.f, 0.f);
            if (row < nrows) {
                int kk = k0 + a_k;
                const float* p = (kk < K0)
                    ? (A0 + (size_t)row * K0 + kk)
                    : (A1 + (size_t)row * K1 + (kk - K0));
                v = *(const float4*)p;
            }
            As[a_k + 0][a_m] = v.x;
            As[a_k + 1][a_m] = v.y;
            As[a_k + 2][a_m] = v.z;
            As[a_k + 3][a_m] = v.w;
        }
        // B tile: 8 k x 128 cols
        {
            int kk = k0 + b_k;
            const float* p = (kk < K0)
                ? (B0 + (size_t)kk * ncols + colBase + b_n)
                : (B1 + (size_t)(kk - K0) * ncols + colBase + b_n);
            *(float4*)&Bs[b_k][b_n] = *(const float4*)p;
        }
        __syncthreads();
        #pragma unroll
        for (int kk = 0; kk < 8; kk++) {
            float a[8], b[8];
            #pragma unroll
            for (int i = 0; i < 8; i++) a[i] = As[kk][ty * 8 + i];
            #pragma unroll
            for (int j = 0; j < 8; j++) b[j] = Bs[kk][tx * 8 + j];
            #pragma unroll
            for (int i = 0; i < 8; i++)
                #pragma unroll
                for (int j = 0; j < 8; j++)
                    acc[i][j] = fmaf(a[i], b[j], acc[i][j]);
        }
        __syncthreads();
    }

    #pragma unroll
    for (int i = 0; i < 8; i++) {
        int row = rowBase + ty * 8 + i;
        if (row >= nrows) continue;
        #pragma unroll
        for (int j = 0; j < 8; j++) {
            int col = colBase + tx * 8 + j;
            float o = acc[i][j];
            if (bias) o += bias[col];
            if (relu) o = fmaxf(o, 0.0f);
            C[(size_t)row * ncols + col] = o;
        }
    }
}

// ---------------- final: aggregate p1, add q1, pool into graph sums ---------
__global__ void k_final(const void* __restrict__ batch) {
    int n = blockIdx.x;
    int f = threadIdx.x;
    int deg = g_cnt[n];
    int start = g_rowstart[n];
    __shared__ int es[128];
    float acc = 0.0f;
    for (int base = 0; base < deg; base += 128) {
        int m = min(128, deg - base);
        __syncthreads();
        if (f < m) es[f] = g_inlist[start + base + f];
        __syncthreads();
        for (int e = 0; e < m; e++) acc += g_p1[es[e] * 128 + f];
    }
    float h2 = acc * g_dinv[n] + g_q1[n * 128 + f];
    int g = ld_idx(batch, n, g_b64);
    atomicAdd(&g_gsum[g * 128 + f], h2);
    if (f == 0) atomicAdd(&g_gcnt[g], 1);
}

// ---------------- layernorm over feature dim per graph ----------------------
__global__ void k_ln(const float* __restrict__ gamma,
                     const float* __restrict__ beta,
                     float* __restrict__ out) {
    int g = blockIdx.x;
    int f = threadIdx.x;
    __shared__ float sh[128];
    float v = g_gsum[g * 128 + f] / fmaxf((float)g_gcnt[g], 1.0f);

    sh[f] = v;
    __syncthreads();
    for (int o = 64; o; o >>= 1) {
        if (f < o) sh[f] += sh[f + o];
        __syncthreads();
    }
    float mean = sh[0] * (1.0f / 128.0f);
    __syncthreads();

    float d = v - mean;
    sh[f] = d * d;
    __syncthreads();
    for (int o = 64; o; o >>= 1) {
        if (f < o) sh[f] += sh[f + o];
        __syncthreads();
    }
    float var = sh[0] * (1.0f / 128.0f);

    out[g * 128 + f] = d * rsqrtf(var + 1e-5f) * gamma[f] + beta[f];
}

// ---------------- launch -----------------------------------------------------
extern "C" void kernel_launch(void* const* d_in, const int* in_sizes, int n_in,
                              void* d_out, int out_size) {
    const float* x     = (const float*)d_in[0];
    const void*  ei    = d_in[1];
    const void*  batch = d_in[2];
    const float* Wl0 = (const float*)d_in[3];
    const float* b0  = (const float*)d_in[4];
    const float* Wr0 = (const float*)d_in[5];
    const float* Wl1 = (const float*)d_in[6];
    const float* b1  = (const float*)d_in[7];
    const float* Wr1 = (const float*)d_in[8];
    const float* Wl2 = (const float*)d_in[9];
    const float* b2  = (const float*)d_in[10];
    const float* Wr2 = (const float*)d_in[11];
    const float* gamma = (const float*)d_in[12];
    const float* beta  = (const float*)d_in[13];
    float* out = (float*)d_out;

    // dtype detection + device pointer table
    k_init<<<1, 32>>>((const int*)ei, (const int*)batch);

    // init + CSR build
    k_zero<<<256, 256>>>();
    k_count<<<512, 256>>>(ei);
    k_scan1<<<NB_SCAN, SCAN_B>>>();
    k_scan2<<<1, 1>>>();
    k_scan3<<<NB_SCAN, SCAN_B>>>();
    k_scatter<<<512, 256>>>(ei);

    // layer 0 (rank-1)
    k_layer0<<<(N_NODES * 32 + 255) / 256, 256>>>(x, Wl0, b0, Wr0);

    // layer 1: gather then fused GEMM  h1 = relu([agg1|h0] @ [Wl1;Wr1] + b1)
    k_gather1<<<N_NODES, 256>>>();
    {
        dim3 grid(256 / 128, (N_NODES + 127) / 128);
        k_sgemm<<<grid, 256>>>(1, 256, 0, 256, Wl1, Wr1, b1, 2,
                               N_NODES, 256, 1);
    }

    // layer 2: compute p1 = h1 @ Wl2, q1 = h1 @ Wr2 + b2 BEFORE aggregation
    {
        dim3 grid(1, (N_NODES + 127) / 128);
        k_sgemm<<<grid, 256>>>(2, 256, -1, 0, Wl2, (const float*)0,
                               (const float*)0, 3, N_NODES, 128, 0);
        k_sgemm<<<grid, 256>>>(2, 256, -1, 0, Wr2, (const float*)0,
                               b2, 4, N_NODES, 128, 0);
    }

    // aggregate p1 (128 feats), add q1, pool into graph sums
    k_final<<<N_NODES, 128>>>(batch);

    // layernorm
    k_ln<<<N_GRAPHS, 128>>>(gamma, beta, out);
}

// round 4
// speedup vs baseline: 1.9767x; 1.9767x over previous
#include <cuda_runtime.h>
#include <cuda_fp16.h>
#include <math.h>

#define N_NODES  50000
#define N_EDGES  800000
#define N_GRAPHS 64
#define SCAN_B   1024
#define NB_SCAN  ((N_NODES + SCAN_B - 1) / SCAN_B)   // 49
#define PA 40   // smem pitch in halves (conflict-free for frag loads)

// ---------------- scratch (device globals; no allocation allowed) ----------
__device__ __align__(16) __half g_h0hi[N_NODES * 256];
__device__ __align__(16) __half g_h0lo[N_NODES * 256];
__device__ __align__(16) __half g_a1hi[N_NODES * 256];
__device__ __align__(16) __half g_a1lo[N_NODES * 256];
__device__ __align__(16) __half g_h1hi[N_NODES * 256];
__device__ __align__(16) __half g_h1lo[N_NODES * 256];
__device__ __align__(16) float  g_pq[N_NODES * 256];    // cols 0-127: p=h1@Wl2, 128-255: q=h1@Wr2+b2
__device__ __align__(16) __half g_W1hi[256 * 512];      // [n][k] k-major, k<256: Wl1, k>=256: Wr1
__device__ __align__(16) __half g_W1lo[256 * 512];
__device__ __align__(16) __half g_W2hi[256 * 256];      // [n][k], n<128: Wl2, n>=128: Wr2
__device__ __align__(16) __half g_W2lo[256 * 256];
__device__ float g_dinv[N_NODES];
__device__ int   g_cnt[N_NODES];
__device__ int   g_rowstart[N_NODES];
__device__ int   g_cursor[N_NODES];
__device__ int   g_inlist[N_EDGES];
__device__ float g_gsum[N_GRAPHS * 128];
__device__ int   g_gcnt[N_GRAPHS];
__device__ int   g_bsums[64];

// dtype flags + device-side half-plane pointer table
__device__ int     g_ei64;
__device__ int     g_b64;
__device__ __half* g_hp[10];  // 0:h0hi 1:h0lo 2:a1hi 3:a1lo 4:h1hi 5:h1lo 6:W1hi 7:W1lo 8:W2hi 9:W2lo

// int64-or-int32 index accessor
__device__ __forceinline__ int ld_idx(const void* p, long long i, int is64) {
    return is64 ? (int)((const long long*)p)[i] : ((const int*)p)[i];
}

__device__ __forceinline__ void split_f32(float v, __half& hi, __half& lo) {
    hi = __float2half_rn(v);
    lo = __float2half_rn(v - __half2float(hi));
}

// ---------------- init: dtype detection + pointer table ---------------------
__global__ void k_init(const int* ei_w, const int* b_w) {
    if (threadIdx.x == 0 && blockIdx.x == 0) {
        int a = 1;
        for (int k = 0; k < 64; k++) if (ei_w[2 * k + 1] != 0) { a = 0; break; }
        g_ei64 = a;
        a = 1;
        for (int k = 0; k < 64; k++) if (b_w[49001 + 2 * k] != 0) { a = 0; break; }
        g_b64 = a;

        g_hp[0] = g_h0hi; g_hp[1] = g_h0lo;
        g_hp[2] = g_a1hi; g_hp[3] = g_a1lo;
        g_hp[4] = g_h1hi; g_hp[5] = g_h1lo;
        g_hp[6] = g_W1hi; g_hp[7] = g_W1lo;
        g_hp[8] = g_W2hi; g_hp[9] = g_W2lo;
    }
}

// ---------------- zero ------------------------------------------------------
__global__ void k_zero() {
    int i = blockIdx.x * blockDim.x + threadIdx.x;
    int stride = gridDim.x * blockDim.x;
    for (int j = i; j < N_NODES; j += stride) g_cnt[j] = 0;
    for (int j = i; j < N_GRAPHS * 128; j += stride) g_gsum[j] = 0.0f;
    for (int j = i; j < N_GRAPHS; j += stride) g_gcnt[j] = 0;
}

// ---------------- weight split-precompute -----------------------------------
__global__ void k_wconv(const float* __restrict__ Wl1, const float* __restrict__ Wr1,
                        const float* __restrict__ Wl2, const float* __restrict__ Wr2) {
    int i = blockIdx.x * blockDim.x + threadIdx.x;
    if (i < 131072) {                       // W1: [n=256][k=512]
        int n = i >> 9, k = i & 511;
        float w = (k < 256) ? Wl1[k * 256 + n] : Wr1[(k - 256) * 256 + n];
        split_f32(w, g_W1hi[i], g_W1lo[i]);
    } else if (i < 196608) {                // W2: [n=256][k=256]
        int j = i - 131072;
        int n = j >> 8, k = j & 255;
        float w = (n < 128) ? Wl2[k * 128 + n] : Wr2[k * 128 + (n - 128)];
        split_f32(w, g_W2hi[j], g_W2lo[j]);
    }
}

// ---------------- CSR build -------------------------------------------------
__global__ void k_count(const void* __restrict__ ei) {
    int is64 = g_ei64;
    int i = blockIdx.x * blockDim.x + threadIdx.x;
    int stride = gridDim.x * blockDim.x;
    for (int e = i; e < N_EDGES; e += stride) {
        int d = ld_idx(ei, (long long)N_EDGES + e, is64);
        atomicAdd(&g_cnt[d], 1);
    }
}

__global__ void k_scan1() {
    __shared__ int s[SCAN_B];
    int i = blockIdx.x * SCAN_B + threadIdx.x;
    int v = (i < N_NODES) ? g_cnt[i] : 0;
    s[threadIdx.x] = v;
    __syncthreads();
    for (int off = 1; off < SCAN_B; off <<= 1) {
        int t = (threadIdx.x >= off) ? s[threadIdx.x - off] : 0;
        __syncthreads();
        s[threadIdx.x] += t;
        __syncthreads();
    }
    if (i < N_NODES) g_rowstart[i] = s[threadIdx.x];
    if (threadIdx.x == SCAN_B - 1) g_bsums[blockIdx.x] = s[SCAN_B - 1];
}

__global__ void k_scan2() {
    int run = 0;
    for (int b = 0; b < NB_SCAN; b++) {
        int t = g_bsums[b];
        g_bsums[b] = run;
        run += t;
    }
}

__global__ void k_scan3() {
    int i = blockIdx.x * SCAN_B + threadIdx.x;
    if (i >= N_NODES) return;
    int incl = g_rowstart[i];
    int excl = incl - g_cnt[i] + g_bsums[i >> 10];
    g_rowstart[i] = excl;
    g_cursor[i] = excl;
}

__global__ void k_scatter(const void* __restrict__ ei) {
    int is64 = g_ei64;
    int i = blockIdx.x * blockDim.x + threadIdx.x;
    int stride = gridDim.x * blockDim.x;
    for (int e = i; e < N_EDGES; e += stride) {
        int s = ld_idx(ei, e, is64);
        int d = ld_idx(ei, (long long)N_EDGES + e, is64);
        int pos = atomicAdd(&g_cursor[d], 1);
        g_inlist[pos] = s;
    }
}

// ---------------- layer 0 (rank-1): warp per node ---------------------------
__global__ void k_layer0(const float* __restrict__ x,
                         const float* __restrict__ Wl0,
                         const float* __restrict__ b0,
                         const float* __restrict__ Wr0) {
    int wid = (blockIdx.x * blockDim.x + threadIdx.x) >> 5;
    int lane = threadIdx.x & 31;
    if (wid >= N_NODES) return;
    int deg = g_cnt[wid];
    int start = g_rowstart[wid];
    float s = 0.0f;
    for (int i = lane; i < deg; i += 32) s += x[g_inlist[start + i]];
    #pragma unroll
    for (int o = 16; o; o >>= 1) s += __shfl_xor_sync(0xFFFFFFFFu, s, o);
    float dinv = 1.0f / fmaxf((float)deg, 1.0f);
    if (lane == 0) g_dinv[wid] = dinv;
    float agg = s * dinv;
    float xv = x[wid];
    #pragma unroll
    for (int i = 0; i < 8; i++) {
        int f = i * 32 + lane;
        float v = fmaf(agg, Wl0[f], fmaf(xv, Wr0[f], b0[f]));
        v = fmaxf(v, 0.0f);
        __half hi, lo;
        split_f32(v, hi, lo);
        g_h0hi[wid * 256 + f] = hi;
        g_h0lo[wid * 256 + f] = lo;
    }
}

// ---------------- gather (mean-aggregate h0 -> a1 planes): block per node ---
__global__ void k_gather1() {
    int n = blockIdx.x;
    int f2 = threadIdx.x;                  // feature pair id: features 2*f2, 2*f2+1
    int deg = g_cnt[n];
    int start = g_rowstart[n];
    __shared__ int es[128];
    float ax = 0.0f, ay = 0.0f;
    for (int base = 0; base < deg; base += 128) {
        int m = min(128, deg - base);
        __syncthreads();
        if (f2 < m) es[f2] = g_inlist[start + base + f2];
        __syncthreads();
        for (int e = 0; e < m; e++) {
            int r = es[e];
            __half2 h = *(const __half2*)&g_h0hi[(size_t)r * 256 + 2 * f2];
            __half2 l = *(const __half2*)&g_h0lo[(size_t)r * 256 + 2 * f2];
            float2 fh = __half22float2(h);
            float2 fl = __half22float2(l);
            ax += fh.x + fl.x;
            ay += fh.y + fl.y;
        }
    }
    float dinv = g_dinv[n];
    ax *= dinv; ay *= dinv;
    __half hx, lx, hy, ly;
    split_f32(ax, hx, lx);
    split_f32(ay, hy, ly);
    *(__half2*)&g_a1hi[(size_t)n * 256 + 2 * f2] = __halves2half2(hx, hy);
    *(__half2*)&g_a1lo[(size_t)n * 256 + 2 * f2] = __halves2half2(lx, ly);
}

// ---------------- split-fp16 tensor-core GEMM --------------------------------
// C[nrows x ncols] = act( [A0|A1] @ B^T + bias ), B stored [n][K] K-major planes.
// 3-term split: Ahi*Bhi + Ahi*Blo + Alo*Bhi (fp32 accumulate).
// BM=128, BN=128, BK=32. 256 threads = 8 warps (2 m x 4 n), warp tile 64x32.
__device__ __forceinline__ void mma16816(float* d, const unsigned* a, const unsigned* b) {
    asm volatile(
        "mma.sync.aligned.m16n8k16.row.col.f32.f16.f16.f32 "
        "{%0,%1,%2,%3}, {%4,%5,%6,%7}, {%8,%9}, {%0,%1,%2,%3};\n"
        : "+f"(d[0]), "+f"(d[1]), "+f"(d[2]), "+f"(d[3])
        : "r"(a[0]), "r"(a[1]), "r"(a[2]), "r"(a[3]), "r"(b[0]), "r"(b[1]));
}

__global__ void __launch_bounds__(256, 2)
k_hgemm(int sA0, int K0, int sA1, int K1, int sB,
        const float* __restrict__ bias, int bias_from, int relu,
        int outHalf, int sOutHi, int nrows, int ncols) {
    const __half* A0h = g_hp[sA0];
    const __half* A0l = g_hp[sA0 + 1];
    const __half* A1h = (sA1 >= 0) ? g_hp[sA1] : (const __half*)0;
    const __half* A1l = (sA1 >= 0) ? g_hp[sA1 + 1] : (const __half*)0;
    const __half* Bh = g_hp[sB];
    const __half* Bl = g_hp[sB + 1];
    __half* Oh = outHalf ? g_hp[sOutHi] : (__half*)0;
    __half* Ol = outHalf ? g_hp[sOutHi + 1] : (__half*)0;

    __shared__ __half As[2][128 * PA];
    __shared__ __half Bs[2][128 * PA];

    int tid = threadIdx.x;
    int lane = tid & 31;
    int wid = tid >> 5;
    int wm = wid & 1;          // 0..1  -> 64-row slab
    int wn = wid >> 1;         // 0..3  -> 32-col slab
    int g = lane >> 2;         // group 0..7
    int t2 = (lane & 3) * 2;   // k/col pair offset
    int rowBase = blockIdx.y * 128;
    int colBase = blockIdx.x * 128;
    int K = K0 + K1;

    float c[4][4][4];
    #pragma unroll
    for (int i = 0; i < 4; i++)
        #pragma unroll
        for (int j = 0; j < 4; j++)
            #pragma unroll
            for (int q = 0; q < 4; q++) c[i][j][q] = 0.0f;

    for (int k0 = 0; k0 < K; k0 += 32) {
        // ---- stage A (128 rows x 32 k, hi+lo) ----
        #pragma unroll
        for (int it = 0; it < 2; it++) {
            int ch = tid + it * 256;           // 0..511
            int r = ch >> 2;
            int kc = (ch & 3) * 8;
            int row = rowBase + r;
            int kk = k0 + kc;
            uint4 vh = make_uint4(0, 0, 0, 0), vl = make_uint4(0, 0, 0, 0);
            if (row < nrows) {
                if (kk < K0) {
                    vh = *(const uint4*)&A0h[(size_t)row * K0 + kk];
                    vl = *(const uint4*)&A0l[(size_t)row * K0 + kk];
                } else {
                    vh = *(const uint4*)&A1h[(size_t)row * K1 + (kk - K0)];
                    vl = *(const uint4*)&A1l[(size_t)row * K1 + (kk - K0)];
                }
            }
            *(uint4*)&As[0][r * PA + kc] = vh;
            *(uint4*)&As[1][r * PA + kc] = vl;
        }
        // ---- stage B (128 cols x 32 k, hi+lo) ----
        #pragma unroll
        for (int it = 0; it < 2; it++) {
            int ch = tid + it * 256;
            int n = ch >> 2;
            int kc = (ch & 3) * 8;
            int col = colBase + n;
            int kk = k0 + kc;
            uint4 vh = *(const uint4*)&Bh[(size_t)col * K + kk];
            uint4 vl = *(const uint4*)&Bl[(size_t)col * K + kk];
            *(uint4*)&Bs[0][n * PA + kc] = vh;
            *(uint4*)&Bs[1][n * PA + kc] = vl;
        }
        __syncthreads();

        // ---- compute 2 x k16 ----
        #pragma unroll
        for (int ks = 0; ks < 2; ks++) {
            int kb = ks * 16;
            unsigned af[4][4], bfh[4][2], bfl[4][2];
            // A hi frags (4 m-tiles)
            #pragma unroll
            for (int mt = 0; mt < 4; mt++) {
                int rb = wm * 64 + mt * 16;
                af[mt][0] = *(const unsigned*)&As[0][(rb + g) * PA + kb + t2];
                af[mt][1] = *(const unsigned*)&As[0][(rb + g + 8) * PA + kb + t2];
                af[mt][2] = *(const unsigned*)&As[0][(rb + g) * PA + kb + t2 + 8];
                af[mt][3] = *(const unsigned*)&As[0][(rb + g + 8) * PA + kb + t2 + 8];
            }
            // B hi + lo frags (4 n-tiles)
            #pragma unroll
            for (int nt = 0; nt < 4; nt++) {
                int nb = wn * 32 + nt * 8 + g;
                bfh[nt][0] = *(const unsigned*)&Bs[0][nb * PA + kb + t2];
                bfh[nt][1] = *(const unsigned*)&Bs[0][nb * PA + kb + t2 + 8];
                bfl[nt][0] = *(const unsigned*)&Bs[1][nb * PA + kb + t2];
                bfl[nt][1] = *(const unsigned*)&Bs[1][nb * PA + kb + t2 + 8];
            }
            // Ahi*Bhi + Ahi*Blo
            #pragma unroll
            for (int mt = 0; mt < 4; mt++)
                #pragma unroll
                for (int nt = 0; nt < 4; nt++) {
                    mma16816(c[mt][nt], af[mt], bfh[nt]);
                    mma16816(c[mt][nt], af[mt], bfl[nt]);
                }
            // A lo frags (reuse regs)
            #pragma unroll
            for (int mt = 0; mt < 4; mt++) {
                int rb = wm * 64 + mt * 16;
                af[mt][0] = *(const unsigned*)&As[1][(rb + g) * PA + kb + t2];
                af[mt][1] = *(const unsigned*)&As[1][(rb + g + 8) * PA + kb + t2];
                af[mt][2] = *(const unsigned*)&As[1][(rb + g) * PA + kb + t2 + 8];
                af[mt][3] = *(const unsigned*)&As[1][(rb + g + 8) * PA + kb + t2 + 8];
            }
            // Alo*Bhi
            #pragma unroll
            for (int mt = 0; mt < 4; mt++)
                #pragma unroll
                for (int nt = 0; nt < 4; nt++)
                    mma16816(c[mt][nt], af[mt], bfh[nt]);
        }
        __syncthreads();
    }

    // ---- epilogue ----
    #pragma unroll
    for (int mt = 0; mt < 4; mt++) {
        #pragma unroll
        for (int nt = 0; nt < 4; nt++) {
            int r0 = rowBase + wm * 64 + mt * 16 + g;
            int cc = colBase + wn * 32 + nt * 8 + t2;
            float bv0 = 0.0f, bv1 = 0.0f;
            if (bias) {
                if (cc >= bias_from)     bv0 = bias[cc - bias_from];
                if (cc + 1 >= bias_from) bv1 = bias[cc + 1 - bias_from];
            }
            #pragma unroll
            for (int half_ : {0, 1}) {
                int row = r0 + half_ * 8;
                if (row >= nrows) continue;
                float v0 = c[mt][nt][half_ * 2 + 0] + bv0;
                float v1 = c[mt][nt][half_ * 2 + 1] + bv1;
                if (relu) { v0 = fmaxf(v0, 0.0f); v1 = fmaxf(v1, 0.0f); }
                if (outHalf) {
                    __half h0, l0, h1, l1;
                    split_f32(v0, h0, l0);
                    split_f32(v1, h1, l1);
                    *(__half2*)&Oh[(size_t)row * ncols + cc] = __halves2half2(h0, h1);
                    *(__half2*)&Ol[(size_t)row * ncols + cc] = __halves2half2(l0, l1);
                } else {
                    *(float2*)&g_pq[(size_t)row * ncols + cc] = make_float2(v0, v1);
                }
            }
        }
    }
}

// ---------------- final: aggregate p, add q, pool into graph sums -----------
__global__ void k_final(const void* __restrict__ batch) {
    int n = blockIdx.x;
    int f = threadIdx.x;
    int deg = g_cnt[n];
    int start = g_rowstart[n];
    __shared__ int es[128];
    float acc = 0.0f;
    for (int base = 0; base < deg; base += 128) {
        int m = min(128, deg - base);
        __syncthreads();
        if (f < m) es[f] = g_inlist[start + base + f];
        __syncthreads();
        for (int e = 0; e < m; e++) acc += g_pq[(size_t)es[e] * 256 + f];
    }
    float h2 = acc * g_dinv[n] + g_pq[(size_t)n * 256 + 128 + f];
    int g = ld_idx(batch, n, g_b64);
    atomicAdd(&g_gsum[g * 128 + f], h2);
    if (f == 0) atomicAdd(&g_gcnt[g], 1);
}

// ---------------- layernorm over feature dim per graph ----------------------
__global__ void k_ln(const float* __restrict__ gamma,
                     const float* __restrict__ beta,
                     float* __restrict__ out) {
    int g = blockIdx.x;
    int f = threadIdx.x;
    __shared__ float sh[128];
    float v = g_gsum[g * 128 + f] / fmaxf((float)g_gcnt[g], 1.0f);

    sh[f] = v;
    __syncthreads();
    for (int o = 64; o; o >>= 1) {
        if (f < o) sh[f] += sh[f + o];
        __syncthreads();
    }
    float mean = sh[0] * (1.0f / 128.0f);
    __syncthreads();

    float d = v - mean;
    sh[f] = d * d;
    __syncthreads();
    for (int o = 64; o; o >>= 1) {
        if (f < o) sh[f] += sh[f + o];
        __syncthreads();
    }
    float var = sh[0] * (1.0f / 128.0f);

    out[g * 128 + f] = d * rsqrtf(var + 1e-5f) * gamma[f] + beta[f];
}

// ---------------- launch -----------------------------------------------------
extern "C" void kernel_launch(void* const* d_in, const int* in_sizes, int n_in,
                              void* d_out, int out_size) {
    const float* x     = (const float*)d_in[0];
    const void*  ei    = d_in[1];
    const void*  batch = d_in[2];
    const float* Wl0 = (const float*)d_in[3];
    const float* b0  = (const float*)d_in[4];
    const float* Wr0 = (const float*)d_in[5];
    const float* Wl1 = (const float*)d_in[6];
    const float* b1  = (const float*)d_in[7];
    const float* Wr1 = (const float*)d_in[8];
    const float* Wl2 = (const float*)d_in[9];
    const float* b2  = (const float*)d_in[10];
    const float* Wr2 = (const float*)d_in[11];
    const float* gamma = (const float*)d_in[12];
    const float* beta  = (const float*)d_in[13];
    float* out = (float*)d_out;

    // dtype detection + device pointer table
    k_init<<<1, 32>>>((const int*)ei, (const int*)batch);

    // init + weight split + CSR build
    k_zero<<<256, 256>>>();
    k_wconv<<<(196608 + 255) / 256, 256>>>(Wl1, Wr1, Wl2, Wr2);
    k_count<<<512, 256>>>(ei);
    k_scan1<<<NB_SCAN, SCAN_B>>>();
    k_scan2<<<1, 1>>>();
    k_scan3<<<NB_SCAN, SCAN_B>>>();
    k_scatter<<<512, 256>>>(ei);

    // layer 0 (rank-1) -> h0 planes
    k_layer0<<<(N_NODES * 32 + 255) / 256, 256>>>(x, Wl0, b0, Wr0);

    // layer 1: gather h0 -> a1 planes, then h1 = relu([a1|h0] @ [Wl1;Wr1] + b1)
    k_gather1<<<N_NODES, 128>>>();
    {
        dim3 grid(2, (N_NODES + 127) / 128);
        k_hgemm<<<grid, 256>>>(2, 256, 0, 256, 6, b1, 0, 1, 1, 4, N_NODES, 256);
    }

    // layer 2 fused: g_pq = h1 @ [Wl2 | Wr2], bias b2 on cols >= 128
    {
        dim3 grid(2, (N_NODES + 127) / 128);
        k_hgemm<<<grid, 256>>>(4, 256, -1, 0, 8, b2, 128, 0, 0, 0, N_NODES, 256);
    }

    // aggregate p, add q, pool into graph sums
    k_final<<<N_NODES, 128>>>(batch);

    // layernorm
    k_ln<<<N_GRAPHS, 128>>>(gamma, beta, out);
}